// round 5
// baseline (speedup 1.0000x reference)
#include <cuda_runtime.h>

#define B_    32
#define CIN   128
#define COUT  256
#define HH    64
#define WW    64
#define TAPS  9
#define PDROP 0.2f

// Per-sample masked + transposed weights: layout [b][tap][cin][cout] (cout fastest)
// 32*9*128*256*4 = 36 MB static device scratch (allocation-free rule).
__device__ float g_wT[B_ * TAPS * CIN * COUT];

// ---------------------------------------------------------------------------
// Kernel 1: apply dropout mask and transpose weights into GEMM-friendly layout
// idx = ((b*9 + t)*128 + i)*256 + o   (coalesced writes)
// ---------------------------------------------------------------------------
__global__ void prep_kernel(const float* __restrict__ w,
                            const float* __restrict__ u_w) {
    int idx = blockIdx.x * 256 + threadIdx.x;          // 0 .. 9437183
    int o = idx & (COUT - 1);
    int i = (idx >> 8) & (CIN - 1);
    int bt = idx >> 15;                                 // b*9 + t
    int t = bt % TAPS;
    int b = bt / TAPS;
    float u  = u_w[((b * COUT + o) * CIN + i) * TAPS + t];
    float wv = w[(o * CIN + i) * TAPS + t];
    g_wT[idx] = (u > PDROP) ? wv : 0.0f;
}

// ---------------------------------------------------------------------------
// Kernel 2: per-sample conv as 9 shifted 1x1-conv GEMMs.
// Block tile: 128 (Cout) x 128 (spatial = 2 rows x 64 cols), K streamed in
// chunks of 8 channels, double-buffered smem, 8x8 register micro-tile built
// from two conflict-free 4-wide strips per dimension.
// ---------------------------------------------------------------------------
__global__ __launch_bounds__(256, 2)
void conv_kernel(const float* __restrict__ x,
                 const float* __restrict__ bias,
                 const float* __restrict__ u_b,
                 float* __restrict__ out) {
    __shared__ float As[2][8][128];   // [buf][kc][m]
    __shared__ float Bs[2][8][128];   // [buf][kc][n]

    const int tid   = threadIdx.x;
    const int b     = blockIdx.z;
    const int m0    = blockIdx.y * 128;   // Cout tile offset
    const int ntile = blockIdx.x;         // spatial tile (2 output rows)
    const int y0    = ntile * 2;

    const int tx = tid & 15;   // N dim: strips at tx*4 and 64+tx*4
    const int ty = tid >> 4;   // M dim: strips at ty*4 and 64+ty*4

    float acc[8][8];
#pragma unroll
    for (int i = 0; i < 8; i++)
#pragma unroll
        for (int j = 0; j < 8; j++) acc[i][j] = 0.0f;

    // staging thread mapping
    const int a_row = tid >> 5;          // 0..7 (k within chunk)
    const int a_col = (tid & 31) * 4;    // 0..124 (m, float4)
    const int lane  = tid & 31;

    const float* xb  = x + (size_t)b * CIN * HH * WW;
    const float* wTb = g_wT + (size_t)b * TAPS * CIN * COUT;

    float a_reg[4];
    float b_reg[4];

    auto load_chunk = [&](int c) {
        const int t   = c >> 4;          // tap 0..8
        const int kc0 = (c & 15) * 8;    // channel chunk base
        // A: weights (coalesced float4)
        const float* ap = wTb + ((size_t)(t * CIN + kc0 + a_row)) * COUT + m0 + a_col;
        float4 av = *(const float4*)ap;
        a_reg[0] = av.x; a_reg[1] = av.y; a_reg[2] = av.z; a_reg[3] = av.w;
        // B: shifted input rows with zero padding
        const int dy = t / 3 - 1;
        const int dx = t % 3 - 1;
        const float* xp = xb + (size_t)(kc0 + a_row) * HH * WW;
#pragma unroll
        for (int j = 0; j < 4; j++) {
            int n  = lane + j * 32;      // 0..127 within spatial tile
            int r  = n >> 6;             // 0/1 (row within tile)
            int cc = n & 63;             // column
            int y  = y0 + r + dy;
            int xx = cc + dx;
            b_reg[j] = (y >= 0 && y < HH && xx >= 0 && xx < WW)
                           ? xp[y * WW + xx] : 0.0f;
        }
    };

    auto store_chunk = [&](int buf) {
        *(float4*)&As[buf][a_row][a_col] =
            make_float4(a_reg[0], a_reg[1], a_reg[2], a_reg[3]);
#pragma unroll
        for (int j = 0; j < 4; j++) Bs[buf][a_row][lane + j * 32] = b_reg[j];
    };

    const int NCH = TAPS * (CIN / 8);    // 144 chunks
    load_chunk(0);
    store_chunk(0);
    __syncthreads();

    for (int c = 0; c < NCH; c++) {
        const int buf = c & 1;
        if (c + 1 < NCH) load_chunk(c + 1);

#pragma unroll
        for (int kc = 0; kc < 8; kc++) {
            float a_frag[8], b_frag[8];
            // Conflict-free split-strip fragment loads: each LDS.128 phase
            // (8 threads) covers a contiguous 128B span of shared memory.
            *(float4*)&a_frag[0] = *(const float4*)&As[buf][kc][ty * 4];
            *(float4*)&a_frag[4] = *(const float4*)&As[buf][kc][64 + ty * 4];
            *(float4*)&b_frag[0] = *(const float4*)&Bs[buf][kc][tx * 4];
            *(float4*)&b_frag[4] = *(const float4*)&Bs[buf][kc][64 + tx * 4];
#pragma unroll
            for (int mm = 0; mm < 8; mm++)
#pragma unroll
                for (int nn = 0; nn < 8; nn++)
                    acc[mm][nn] = fmaf(a_frag[mm], b_frag[nn], acc[mm][nn]);
        }

        if (c + 1 < NCH) store_chunk(buf ^ 1);
        __syncthreads();
    }

    // Epilogue: add per-sample dropped bias, write fp32 output.
    // n-strips: nn<4 -> row y0, col tx*4+nn ; nn>=4 -> row y0+1, col tx*4+(nn-4)
    // m-strips: mm<4 -> o = m0+ty*4+mm   ; mm>=4 -> o = m0+64+ty*4+(mm-4)
#pragma unroll
    for (int mm = 0; mm < 8; mm++) {
        const int m  = (mm < 4) ? (ty * 4 + mm) : (64 + ty * 4 + (mm - 4));
        const int o  = m0 + m;
        const float bv = (u_b[b * COUT + o] > PDROP) ? bias[o] : 0.0f;
        float* op = out + (((size_t)b * COUT + o) * HH + y0) * WW + tx * 4;
        float4 v0 = make_float4(acc[mm][0] + bv, acc[mm][1] + bv,
                                acc[mm][2] + bv, acc[mm][3] + bv);
        float4 v1 = make_float4(acc[mm][4] + bv, acc[mm][5] + bv,
                                acc[mm][6] + bv, acc[mm][7] + bv);
        *(float4*)op            = v0;   // row y0
        *(float4*)(op + WW)     = v1;   // row y0 + 1
    }
}

// ---------------------------------------------------------------------------
extern "C" void kernel_launch(void* const* d_in, const int* in_sizes, int n_in,
                              void* d_out, int out_size) {
    // Identify inputs by element count (robust to metadata ordering).
    const float* x    = nullptr;   // 32*128*64*64 = 16777216
    const float* w    = nullptr;   // 256*128*9    = 294912
    const float* bias = nullptr;   // 256
    const float* u_w  = nullptr;   // 32*256*128*9 = 9437184
    const float* u_b  = nullptr;   // 32*256       = 8192
    for (int i = 0; i < n_in; i++) {
        switch (in_sizes[i]) {
            case 16777216: x    = (const float*)d_in[i]; break;
            case 294912:   w    = (const float*)d_in[i]; break;
            case 256:      bias = (const float*)d_in[i]; break;
            case 9437184:  u_w  = (const float*)d_in[i]; break;
            case 8192:     u_b  = (const float*)d_in[i]; break;
            default: break;
        }
    }
    float* out = (float*)d_out;

    prep_kernel<<<(B_ * TAPS * CIN * COUT) / 256, 256>>>(w, u_w);

    dim3 grid(32, 2, 32);   // (ntile, mtile, batch)
    conv_kernel<<<grid, 256>>>(x, bias, u_b, out);
}

// round 11
// speedup vs baseline: 3.3063x; 3.3063x over previous
#include <cuda_runtime.h>
#include <cstdint>

#define B_    32
#define CIN   128
#define COUT  256
#define HH    64
#define WW    64
#define TAPS  9
#define PDROP 0.2f

#define KTOT   (TAPS * CIN)     // 1152
#define NCHUNK (KTOT / 32)      // 36 chunks of K=32

// tf32-rounded fp32 operands in GEMM-friendly layouts (static scratch; no allocs)
__device__ float g_wA[B_ * COUT * KTOT];        // [b][o][k], k = tap*128+ci  (37.7 MB)
__device__ float g_xT[B_ * HH * WW * CIN];      // [b][y][x][ci] channel-last (67 MB)

__device__ __forceinline__ float to_tf32(float v) {
    uint32_t r;
    asm("cvt.rna.tf32.f32 %0, %1;" : "=r"(r) : "f"(v));
    return __uint_as_float(r);
}
__device__ __forceinline__ uint32_t smem_u32(const void* p) {
    uint32_t a;
    asm("{ .reg .u64 t; cvta.to.shared.u64 t, %1; cvt.u32.u64 %0, t; }" : "=r"(a) : "l"(p));
    return a;
}

// ---------------------------------------------------------------------------
// prep_w: dropout-mask weights, reorder to [b][o][k] (k fastest), tf32 round
// ---------------------------------------------------------------------------
__global__ void prep_w(const float* __restrict__ w, const float* __restrict__ u_w) {
    int idx = blockIdx.x * 256 + threadIdx.x;        // [b][o][k]
    int k  = idx % KTOT;
    int bo = idx / KTOT;
    int o  = bo % COUT;
    int b  = bo / COUT;
    int t  = k >> 7;
    int ci = k & 127;
    float u  = u_w[((b * COUT + o) * CIN + ci) * TAPS + t];
    float wv = w[(o * CIN + ci) * TAPS + t];
    g_wA[idx] = to_tf32((u > PDROP) ? wv : 0.0f);
}

// ---------------------------------------------------------------------------
// prep_x: NCHW -> channel-last [b][y][x][ci], tf32 round
// ---------------------------------------------------------------------------
__global__ void prep_x(const float* __restrict__ x) {
    __shared__ float tile[32][33];
    const int lane = threadIdx.x;                    // 32
    const int ty   = threadIdx.y;                    // 8
    const int x0   = (blockIdx.x & 1) * 32;
    const int ci0  = (blockIdx.x >> 1) * 32;
    const int y    = blockIdx.y;
    const int b    = blockIdx.z;
    const float* xp = x + (((size_t)b * CIN + ci0) * HH + y) * WW + x0;
#pragma unroll
    for (int ii = 0; ii < 4; ii++) {
        int i = ty * 4 + ii;
        tile[i][lane] = xp[(size_t)i * HH * WW + lane];
    }
    __syncthreads();
    float* op = g_xT + (((size_t)b * HH + y) * WW + x0) * CIN + ci0;
#pragma unroll
    for (int jj = 0; jj < 4; jj++) {
        int j = ty * 4 + jj;
        op[(size_t)j * CIN + lane] = to_tf32(tile[lane][j]);
    }
}

// ---------------------------------------------------------------------------
// conv_mma: per-sample implicit-GEMM conv on mma.sync tf32 (HMMA).
// CTA tile M=128 (Cout) x N=128 (2 rows x 64 cols) x K=1152 (36 chunks of 32).
// smem tiles As[128][36], Bs[128][36] (k-major, pad->36 : conflict-free LDS),
// filled by predicated cp.async.cg 16B, 2-deep pipeline.
// ---------------------------------------------------------------------------
#define TSTRIDE 36
#define TILE_F  (128 * TSTRIDE)                      // floats per tile
#define SMEM_BYTES (4 * TILE_F * 4)                  // 73728

__global__ __launch_bounds__(256, 2)
void conv_mma(const float* __restrict__ bias,
              const float* __restrict__ u_b,
              float* __restrict__ out) {
    extern __shared__ float smem[];
    float* As = smem;                                // [2][128][36]
    float* Bs = smem + 2 * TILE_F;                   // [2][128][36]

    const int tid  = threadIdx.x;
    const int wid  = tid >> 5;
    const int lane = tid & 31;
    const int b    = blockIdx.z;
    const int m0   = blockIdx.y * 128;
    const int y0   = blockIdx.x * 2;

    const int wm  = (wid & 1) * 64;                  // warp M offset
    const int wn  = (wid >> 1) * 32;                 // warp N offset
    const int row = lane >> 2;                       // 0..7
    const int kq  = lane & 3;                        // 0..3

    float acc[4][4][4];
#pragma unroll
    for (int i = 0; i < 4; i++)
#pragma unroll
        for (int j = 0; j < 4; j++)
#pragma unroll
            for (int r = 0; r < 4; r++) acc[i][j][r] = 0.0f;

    const float* wAb = g_wA + (size_t)(b * COUT + m0) * KTOT;
    const float* xTb = g_xT + (size_t)b * HH * WW * CIN;

    auto stage = [&](int c, int buf) {
        const int t   = c >> 2;
        const int ci0 = (c & 3) * 32;
        const int dy  = t / 3 - 1;
        const int dx  = t % 3 - 1;
        float* Ab = As + buf * TILE_F;
        float* Bb = Bs + buf * TILE_F;
#pragma unroll
        for (int it = 0; it < 4; it++) {             // A: 128 rows x 8 quads
            int q = tid + 256 * it;
            int m = q >> 3, k4 = (q & 7) * 4;
            const float* src = wAb + (size_t)m * KTOT + c * 32 + k4;
            uint32_t dst = smem_u32(Ab + m * TSTRIDE + k4);
            asm volatile("cp.async.cg.shared.global [%0], [%1], 16;"
                         :: "r"(dst), "l"(src));
        }
#pragma unroll
        for (int it = 0; it < 4; it++) {             // B: 128 pixels x 8 quads
            int q = tid + 256 * it;
            int n = q >> 3, k4 = (q & 7) * 4;
            int yy = y0 + (n >> 6) + dy;
            int xx = (n & 63) + dx;
            bool inb = (yy >= 0 && yy < HH && xx >= 0 && xx < WW);
            const float* src = xTb + ((size_t)((inb ? yy : 0) * WW + (inb ? xx : 0))) * CIN
                               + ci0 + k4;
            uint32_t dst = smem_u32(Bb + n * TSTRIDE + k4);
            int sz = inb ? 16 : 0;                   // zero-fill halo
            asm volatile("cp.async.cg.shared.global [%0], [%1], 16, %2;"
                         :: "r"(dst), "l"(src), "r"(sz));
        }
    };

    stage(0, 0);
    asm volatile("cp.async.commit_group;");
    stage(1, 1);
    asm volatile("cp.async.commit_group;");

    for (int c = 0; c < NCHUNK; c++) {
        const int buf = c & 1;
        if (c + 2 < NCHUNK) asm volatile("cp.async.wait_group 1;");
        else                asm volatile("cp.async.wait_group 0;");
        __syncthreads();

        const float* Ab = As + buf * TILE_F;
        const float* Bb = Bs + buf * TILE_F;
#pragma unroll
        for (int ks = 0; ks < 4; ks++) {
            const int k0 = ks * 8;
            uint32_t a[4][4];
#pragma unroll
            for (int i = 0; i < 4; i++) {
                const float* ap = Ab + (wm + i * 16 + row) * TSTRIDE + k0 + kq;
                a[i][0] = __float_as_uint(ap[0]);
                a[i][1] = __float_as_uint(ap[8 * TSTRIDE]);
                a[i][2] = __float_as_uint(ap[4]);
                a[i][3] = __float_as_uint(ap[8 * TSTRIDE + 4]);
            }
#pragma unroll
            for (int j = 0; j < 4; j++) {
                const float* bp = Bb + (wn + j * 8 + row) * TSTRIDE + k0 + kq;
                uint32_t b0 = __float_as_uint(bp[0]);
                uint32_t b1 = __float_as_uint(bp[4]);
#pragma unroll
                for (int i = 0; i < 4; i++) {
                    asm volatile(
                        "mma.sync.aligned.m16n8k8.row.col.f32.tf32.tf32.f32 "
                        "{%0,%1,%2,%3}, {%4,%5,%6,%7}, {%8,%9}, {%0,%1,%2,%3};"
                        : "+f"(acc[i][j][0]), "+f"(acc[i][j][1]),
                          "+f"(acc[i][j][2]), "+f"(acc[i][j][3])
                        : "r"(a[i][0]), "r"(a[i][1]), "r"(a[i][2]), "r"(a[i][3]),
                          "r"(b0), "r"(b1));
                }
            }
        }
        __syncthreads();
        if (c + 2 < NCHUNK) {
            stage(c + 2, buf);
            asm volatile("cp.async.commit_group;");
        }
    }

    // ---- epilogue: per-sample dropped bias + float2 stores ----
    const float* ub = u_b + b * COUT;
#pragma unroll
    for (int i = 0; i < 4; i++) {
        const int o0 = m0 + wm + i * 16 + row;
        const float bv0 = (ub[o0]     > PDROP) ? bias[o0]     : 0.0f;
        const float bv1 = (ub[o0 + 8] > PDROP) ? bias[o0 + 8] : 0.0f;
#pragma unroll
        for (int j = 0; j < 4; j++) {
            const int nn = wn + j * 8 + 2 * (lane & 3);
            const int yy = y0 + (nn >> 6);
            const int xx = nn & 63;
            float* p0 = out + ((size_t)(b * COUT + o0)     * HH + yy) * WW + xx;
            float* p1 = out + ((size_t)(b * COUT + o0 + 8) * HH + yy) * WW + xx;
            *(float2*)p0 = make_float2(acc[i][j][0] + bv0, acc[i][j][1] + bv0);
            *(float2*)p1 = make_float2(acc[i][j][2] + bv1, acc[i][j][3] + bv1);
        }
    }
}

// ---------------------------------------------------------------------------
extern "C" void kernel_launch(void* const* d_in, const int* in_sizes, int n_in,
                              void* d_out, int out_size) {
    const float* x    = nullptr;   // 16777216
    const float* w    = nullptr;   // 294912
    const float* bias = nullptr;   // 256
    const float* u_w  = nullptr;   // 9437184
    const float* u_b  = nullptr;   // 8192
    for (int i = 0; i < n_in; i++) {
        switch (in_sizes[i]) {
            case 16777216: x    = (const float*)d_in[i]; break;
            case 294912:   w    = (const float*)d_in[i]; break;
            case 256:      bias = (const float*)d_in[i]; break;
            case 9437184:  u_w  = (const float*)d_in[i]; break;
            case 8192:     u_b  = (const float*)d_in[i]; break;
            default: break;
        }
    }
    float* out = (float*)d_out;

    static bool attr_set = false;
    if (!attr_set) {
        cudaFuncSetAttribute(conv_mma, cudaFuncAttributeMaxDynamicSharedMemorySize,
                             SMEM_BYTES);
        attr_set = true;
    }

    prep_w<<<(B_ * COUT * KTOT) / 256, 256>>>(w, u_w);
    prep_x<<<dim3(8, 64, 32), dim3(32, 8)>>>(x);

    dim3 grid(32, 2, 32);   // (n-tile: 2 rows, m-tile, batch)
    conv_mma<<<grid, 256, SMEM_BYTES>>>(bias, u_b, out);
}

// round 13
// speedup vs baseline: 5.5713x; 1.6850x over previous
#include <cuda_runtime.h>
#include <cuda_fp16.h>
#include <cstdint>

#define B_    32
#define CIN   128
#define COUT  256
#define HH    64
#define WW    64
#define TAPS  9
#define PDROP 0.2f

#define KTOT   (TAPS * CIN)     // 1152
#define NCHUNK (KTOT / 32)      // 36 chunks of K=32

// fp16 operands in GEMM-friendly layouts (static scratch; no allocs)
__device__ __half g_wA[B_ * COUT * KTOT];        // [b][o][k], k = tap*128+ci  (18.9 MB)
__device__ __half g_xT[B_ * HH * WW * CIN];      // [b][y][x][ci] channel-last (33.5 MB)

__device__ __forceinline__ uint32_t smem_u32(const void* p) {
    uint32_t a;
    asm("{ .reg .u64 t; cvta.to.shared.u64 t, %1; cvt.u32.u64 %0, t; }" : "=r"(a) : "l"(p));
    return a;
}

// ---------------------------------------------------------------------------
// prep_w: dropout-mask weights, reorder to [b][o][k] (k fastest), fp16 round
// ---------------------------------------------------------------------------
__global__ void prep_w(const float* __restrict__ w, const float* __restrict__ u_w) {
    int idx = blockIdx.x * 256 + threadIdx.x;        // [b][o][k]
    int k  = idx % KTOT;
    int bo = idx / KTOT;
    int o  = bo % COUT;
    int b  = bo / COUT;
    int t  = k >> 7;
    int ci = k & 127;
    float u  = u_w[((b * COUT + o) * CIN + ci) * TAPS + t];
    float wv = w[(o * CIN + ci) * TAPS + t];
    g_wA[idx] = __float2half_rn((u > PDROP) ? wv : 0.0f);
}

// ---------------------------------------------------------------------------
// prep_x: NCHW -> channel-last [b][y][x][ci], fp16 round
// ---------------------------------------------------------------------------
__global__ void prep_x(const float* __restrict__ x) {
    __shared__ float tile[32][33];
    const int lane = threadIdx.x;                    // 32
    const int ty   = threadIdx.y;                    // 8
    const int x0   = (blockIdx.x & 1) * 32;
    const int ci0  = (blockIdx.x >> 1) * 32;
    const int y    = blockIdx.y;
    const int b    = blockIdx.z;
    const float* xp = x + (((size_t)b * CIN + ci0) * HH + y) * WW + x0;
#pragma unroll
    for (int ii = 0; ii < 4; ii++) {
        int i = ty * 4 + ii;
        tile[i][lane] = xp[(size_t)i * HH * WW + lane];
    }
    __syncthreads();
    __half* op = g_xT + (((size_t)b * HH + y) * WW + x0) * CIN + ci0;
#pragma unroll
    for (int jj = 0; jj < 4; jj++) {
        int j = ty * 4 + jj;
        op[(size_t)j * CIN + lane] = __float2half_rn(tile[lane][j]);
    }
}

// ---------------------------------------------------------------------------
// conv_mma: per-sample implicit-GEMM conv on mma.sync fp16 (HMMA m16n8k16).
// CTA tile M=128 (Cout) x N=128 (2 rows x 64 cols) x K=1152 (36 chunks of 32).
// smem tiles As[128][40], Bs[128][40] halves (pad 40 -> conflict-free LDS),
// filled by predicated cp.async.cg 16B, 2-deep pipeline.
// ---------------------------------------------------------------------------
#define TSTRIDE 40                                   // halves per row (80B)
#define TILE_H  (128 * TSTRIDE)                      // halves per tile
#define SMEM_BYTES (4 * TILE_H * 2)                  // 40960

__global__ __launch_bounds__(256, 2)
void conv_mma(const float* __restrict__ bias,
              const float* __restrict__ u_b,
              float* __restrict__ out) {
    extern __shared__ __half smem[];
    __half* As = smem;                               // [2][128][40]
    __half* Bs = smem + 2 * TILE_H;                  // [2][128][40]

    const int tid  = threadIdx.x;
    const int wid  = tid >> 5;
    const int lane = tid & 31;
    const int b    = blockIdx.z;
    const int m0   = blockIdx.y * 128;
    const int y0   = blockIdx.x * 2;

    const int wm  = (wid & 1) * 64;                  // warp M offset
    const int wn  = (wid >> 1) * 32;                 // warp N offset
    const int row = lane >> 2;                       // 0..7
    const int kq2 = (lane & 3) * 2;                  // 0,2,4,6 (halves)

    float acc[4][4][4];
#pragma unroll
    for (int i = 0; i < 4; i++)
#pragma unroll
        for (int j = 0; j < 4; j++)
#pragma unroll
            for (int r = 0; r < 4; r++) acc[i][j][r] = 0.0f;

    const __half* wAb = g_wA + (size_t)(b * COUT + m0) * KTOT;
    const __half* xTb = g_xT + (size_t)b * HH * WW * CIN;

    auto stage = [&](int c, int buf) {
        const int t   = c >> 2;
        const int ci0 = (c & 3) * 32;
        const int dy  = t / 3 - 1;
        const int dx  = t % 3 - 1;
        __half* Ab = As + buf * TILE_H;
        __half* Bb = Bs + buf * TILE_H;
#pragma unroll
        for (int it = 0; it < 2; it++) {             // A: 128 rows x 4 quads(16B)
            int q = tid + 256 * it;
            int m = q >> 2, k8 = (q & 3) * 8;
            const __half* src = wAb + (size_t)m * KTOT + c * 32 + k8;
            uint32_t dst = smem_u32(Ab + m * TSTRIDE + k8);
            asm volatile("cp.async.cg.shared.global [%0], [%1], 16;"
                         :: "r"(dst), "l"(src));
        }
#pragma unroll
        for (int it = 0; it < 2; it++) {             // B: 128 pixels x 4 quads
            int q = tid + 256 * it;
            int n = q >> 2, k8 = (q & 3) * 8;
            int yy = y0 + (n >> 6) + dy;
            int xx = (n & 63) + dx;
            bool inb = (yy >= 0 && yy < HH && xx >= 0 && xx < WW);
            const __half* src = xTb + ((size_t)((inb ? yy : 0) * WW + (inb ? xx : 0))) * CIN
                                + ci0 + k8;
            uint32_t dst = smem_u32(Bb + n * TSTRIDE + k8);
            int sz = inb ? 16 : 0;                   // zero-fill halo
            asm volatile("cp.async.cg.shared.global [%0], [%1], 16, %2;"
                         :: "r"(dst), "l"(src), "r"(sz));
        }
    };

    stage(0, 0);
    asm volatile("cp.async.commit_group;");
    stage(1, 1);
    asm volatile("cp.async.commit_group;");

    for (int c = 0; c < NCHUNK; c++) {
        const int buf = c & 1;
        if (c + 2 < NCHUNK) asm volatile("cp.async.wait_group 1;");
        else                asm volatile("cp.async.wait_group 0;");
        __syncthreads();

        const __half* Ab = As + buf * TILE_H;
        const __half* Bb = Bs + buf * TILE_H;
#pragma unroll
        for (int ks = 0; ks < 2; ks++) {             // two k16 steps
            const int k0 = ks * 16;
            uint32_t a[4][4];
#pragma unroll
            for (int i = 0; i < 4; i++) {
                const __half* ap = Ab + (wm + i * 16 + row) * TSTRIDE + k0 + kq2;
                a[i][0] = *(const uint32_t*)(ap);
                a[i][1] = *(const uint32_t*)(ap + 8 * TSTRIDE);
                a[i][2] = *(const uint32_t*)(ap + 8);
                a[i][3] = *(const uint32_t*)(ap + 8 * TSTRIDE + 8);
            }
#pragma unroll
            for (int j = 0; j < 4; j++) {
                const __half* bp = Bb + (wn + j * 8 + row) * TSTRIDE + k0 + kq2;
                uint32_t b0 = *(const uint32_t*)(bp);
                uint32_t b1 = *(const uint32_t*)(bp + 8);
#pragma unroll
                for (int i = 0; i < 4; i++) {
                    asm volatile(
                        "mma.sync.aligned.m16n8k16.row.col.f32.f16.f16.f32 "
                        "{%0,%1,%2,%3}, {%4,%5,%6,%7}, {%8,%9}, {%0,%1,%2,%3};"
                        : "+f"(acc[i][j][0]), "+f"(acc[i][j][1]),
                          "+f"(acc[i][j][2]), "+f"(acc[i][j][3])
                        : "r"(a[i][0]), "r"(a[i][1]), "r"(a[i][2]), "r"(a[i][3]),
                          "r"(b0), "r"(b1));
                }
            }
        }
        __syncthreads();
        if (c + 2 < NCHUNK) {
            stage(c + 2, buf);
            asm volatile("cp.async.commit_group;");
        }
    }

    // ---- epilogue: per-sample dropped bias + float2 stores ----
    const float* ub = u_b + b * COUT;
#pragma unroll
    for (int i = 0; i < 4; i++) {
        const int o0 = m0 + wm + i * 16 + row;
        const float bv0 = (ub[o0]     > PDROP) ? bias[o0]     : 0.0f;
        const float bv1 = (ub[o0 + 8] > PDROP) ? bias[o0 + 8] : 0.0f;
#pragma unroll
        for (int j = 0; j < 4; j++) {
            const int nn = wn + j * 8 + 2 * (lane & 3);
            const int yy = y0 + (nn >> 6);
            const int xx = nn & 63;
            float* p0 = out + ((size_t)(b * COUT + o0)     * HH + yy) * WW + xx;
            float* p1 = out + ((size_t)(b * COUT + o0 + 8) * HH + yy) * WW + xx;
            *(float2*)p0 = make_float2(acc[i][j][0] + bv0, acc[i][j][1] + bv0);
            *(float2*)p1 = make_float2(acc[i][j][2] + bv1, acc[i][j][3] + bv1);
        }
    }
}

// ---------------------------------------------------------------------------
extern "C" void kernel_launch(void* const* d_in, const int* in_sizes, int n_in,
                              void* d_out, int out_size) {
    const float* x    = nullptr;   // 16777216
    const float* w    = nullptr;   // 294912
    const float* bias = nullptr;   // 256
    const float* u_w  = nullptr;   // 9437184
    const float* u_b  = nullptr;   // 8192
    for (int i = 0; i < n_in; i++) {
        switch (in_sizes[i]) {
            case 16777216: x    = (const float*)d_in[i]; break;
            case 294912:   w    = (const float*)d_in[i]; break;
            case 256:      bias = (const float*)d_in[i]; break;
            case 9437184:  u_w  = (const float*)d_in[i]; break;
            case 8192:     u_b  = (const float*)d_in[i]; break;
            default: break;
        }
    }
    float* out = (float*)d_out;

    static bool attr_set = false;
    if (!attr_set) {
        cudaFuncSetAttribute(conv_mma, cudaFuncAttributeMaxDynamicSharedMemorySize,
                             SMEM_BYTES);
        attr_set = true;
    }

    prep_w<<<(B_ * COUT * KTOT) / 256, 256>>>(w, u_w);
    prep_x<<<dim3(8, 64, 32), dim3(32, 8)>>>(x);

    dim3 grid(32, 2, 32);   // (n-tile: 2 rows, m-tile, batch)
    conv_mma<<<grid, 256, SMEM_BYTES>>>(bias, u_b, out);
}

// round 15
// speedup vs baseline: 6.4434x; 1.1565x over previous
#include <cuda_runtime.h>
#include <cuda_fp16.h>
#include <cstdint>

#define B_    32
#define CIN   128
#define COUT  256
#define HH    64
#define WW    64
#define TAPS  9
#define PDROP 0.2f

#define KTOT   (TAPS * CIN)     // 1152
#define NCHUNK (KTOT / 32)      // 36 chunks of K=32

// fp16 operands in GEMM-friendly layouts (static scratch; no allocs)
__device__ __half g_wA[B_ * COUT * KTOT];        // [b][o][k], k = tap*128+ci  (18.9 MB)
__device__ __half g_xT[B_ * HH * WW * CIN];      // [b][y][x][ci] channel-last (33.5 MB)

__device__ __forceinline__ uint32_t smem_u32(const void* p) {
    uint32_t a;
    asm("{ .reg .u64 t; cvta.to.shared.u64 t, %1; cvt.u32.u64 %0, t; }" : "=r"(a) : "l"(p));
    return a;
}

#define LDSM4(r0, r1, r2, r3, addr)                                             \
    asm volatile("ldmatrix.sync.aligned.m8n8.x4.shared.b16 {%0,%1,%2,%3}, [%4];" \
                 : "=r"(r0), "=r"(r1), "=r"(r2), "=r"(r3) : "r"(addr))

// ---------------------------------------------------------------------------
// prep_w: dropout-mask weights, reorder to [b][o][k] (k fastest), fp16 round
// ---------------------------------------------------------------------------
__global__ void prep_w(const float* __restrict__ w, const float* __restrict__ u_w) {
    int idx = blockIdx.x * 256 + threadIdx.x;        // [b][o][k]
    int k  = idx % KTOT;
    int bo = idx / KTOT;
    int o  = bo % COUT;
    int b  = bo / COUT;
    int t  = k >> 7;
    int ci = k & 127;
    float u  = u_w[((b * COUT + o) * CIN + ci) * TAPS + t];
    float wv = w[(o * CIN + ci) * TAPS + t];
    g_wA[idx] = __float2half_rn((u > PDROP) ? wv : 0.0f);
}

// ---------------------------------------------------------------------------
// prep_x: NCHW -> channel-last [b][y][x][ci], fp16 round
// ---------------------------------------------------------------------------
__global__ void prep_x(const float* __restrict__ x) {
    __shared__ float tile[32][33];
    const int lane = threadIdx.x;                    // 32
    const int ty   = threadIdx.y;                    // 8
    const int x0   = (blockIdx.x & 1) * 32;
    const int ci0  = (blockIdx.x >> 1) * 32;
    const int y    = blockIdx.y;
    const int b    = blockIdx.z;
    const float* xp = x + (((size_t)b * CIN + ci0) * HH + y) * WW + x0;
#pragma unroll
    for (int ii = 0; ii < 4; ii++) {
        int i = ty * 4 + ii;
        tile[i][lane] = xp[(size_t)i * HH * WW + lane];
    }
    __syncthreads();
    __half* op = g_xT + (((size_t)b * HH + y) * WW + x0) * CIN + ci0;
#pragma unroll
    for (int jj = 0; jj < 4; jj++) {
        int j = ty * 4 + jj;
        op[(size_t)j * CIN + lane] = __float2half_rn(tile[lane][j]);
    }
}

// ---------------------------------------------------------------------------
// conv_mma: per-sample implicit-GEMM conv on mma.sync fp16 (HMMA m16n8k16),
// fragments loaded via ldmatrix.x4 (12 LDSM vs 48 LDS per warp-chunk).
// CTA tile M=128 (Cout) x N=128 (2 rows x 64 cols) x K=1152 (36 chunks of 32).
// smem tiles As[128][40], Bs[128][40] halves (pad 40 -> conflict-free LDSM),
// filled by predicated cp.async.cg 16B, 2-deep pipeline.
// ---------------------------------------------------------------------------
#define TSTRIDE 40                                   // halves per row (80B)
#define TILE_H  (128 * TSTRIDE)                      // halves per tile
#define SMEM_BYTES (4 * TILE_H * 2)                  // 40960

__global__ __launch_bounds__(256, 2)
void conv_mma(const float* __restrict__ bias,
              const float* __restrict__ u_b,
              float* __restrict__ out) {
    extern __shared__ __half smem[];
    __half* As = smem;                               // [2][128][40]
    __half* Bs = smem + 2 * TILE_H;                  // [2][128][40]

    const int tid  = threadIdx.x;
    const int wid  = tid >> 5;
    const int lane = tid & 31;
    const int b    = blockIdx.z;
    const int m0   = blockIdx.y * 128;
    const int y0   = blockIdx.x * 2;

    const int wm  = (wid & 1) * 64;                  // warp M offset
    const int wn  = (wid >> 1) * 32;                 // warp N offset
    const int row = lane >> 2;                       // 0..7

    // Per-lane LDSM base addresses (bytes).
    // A x4 (per i,ks): q0/q1 = m rows 0..15 @k0, q2/q3 = same @k0+8.
    const uint32_t aAddr0 = smem_u32(As) +
        (uint32_t)(((wm + (lane & 15)) * TSTRIDE + (lane >> 4) * 8) * 2);
    // B x4 (per j-pair,ks): q0/q1 = n rows 0..7 @k0/k0+8, q2/q3 = n rows 8..15.
    const uint32_t bAddr0 = smem_u32(Bs) +
        (uint32_t)(((wn + (lane >> 4) * 8 + (lane & 7)) * TSTRIDE +
                    ((lane >> 3) & 1) * 8) * 2);

    float acc[4][4][4];
#pragma unroll
    for (int i = 0; i < 4; i++)
#pragma unroll
        for (int j = 0; j < 4; j++)
#pragma unroll
            for (int r = 0; r < 4; r++) acc[i][j][r] = 0.0f;

    const __half* wAb = g_wA + (size_t)(b * COUT + m0) * KTOT;
    const __half* xTb = g_xT + (size_t)b * HH * WW * CIN;

    auto stage = [&](int c, int buf) {
        const int t   = c >> 2;
        const int ci0 = (c & 3) * 32;
        const int dy  = t / 3 - 1;
        const int dx  = t % 3 - 1;
        __half* Ab = As + buf * TILE_H;
        __half* Bb = Bs + buf * TILE_H;
#pragma unroll
        for (int it = 0; it < 2; it++) {             // A: 128 rows x 4 quads(16B)
            int q = tid + 256 * it;
            int m = q >> 2, k8 = (q & 3) * 8;
            const __half* src = wAb + (size_t)m * KTOT + c * 32 + k8;
            uint32_t dst = smem_u32(Ab + m * TSTRIDE + k8);
            asm volatile("cp.async.cg.shared.global [%0], [%1], 16;"
                         :: "r"(dst), "l"(src));
        }
#pragma unroll
        for (int it = 0; it < 2; it++) {             // B: 128 pixels x 4 quads
            int q = tid + 256 * it;
            int n = q >> 2, k8 = (q & 3) * 8;
            int yy = y0 + (n >> 6) + dy;
            int xx = (n & 63) + dx;
            bool inb = (yy >= 0 && yy < HH && xx >= 0 && xx < WW);
            const __half* src = xTb + ((size_t)((inb ? yy : 0) * WW + (inb ? xx : 0))) * CIN
                                + ci0 + k8;
            uint32_t dst = smem_u32(Bb + n * TSTRIDE + k8);
            int sz = inb ? 16 : 0;                   // zero-fill halo
            asm volatile("cp.async.cg.shared.global [%0], [%1], 16, %2;"
                         :: "r"(dst), "l"(src), "r"(sz));
        }
    };

    stage(0, 0);
    asm volatile("cp.async.commit_group;");
    stage(1, 1);
    asm volatile("cp.async.commit_group;");

    for (int c = 0; c < NCHUNK; c++) {
        const int buf = c & 1;
        if (c + 2 < NCHUNK) asm volatile("cp.async.wait_group 1;");
        else                asm volatile("cp.async.wait_group 0;");
        __syncthreads();

        const uint32_t aA = aAddr0 + (uint32_t)(buf * TILE_H * 2);
        const uint32_t bA = bAddr0 + (uint32_t)(buf * TILE_H * 2);
#pragma unroll
        for (int ks = 0; ks < 2; ks++) {             // two k16 steps
            uint32_t a[4][4];
#pragma unroll
            for (int i = 0; i < 4; i++)
                LDSM4(a[i][0], a[i][1], a[i][2], a[i][3],
                      aA + (uint32_t)((i * 16 * TSTRIDE) * 2 + ks * 32));
            uint32_t bb[2][4];
#pragma unroll
            for (int j2 = 0; j2 < 2; j2++)
                LDSM4(bb[j2][0], bb[j2][1], bb[j2][2], bb[j2][3],
                      bA + (uint32_t)((j2 * 16 * TSTRIDE) * 2 + ks * 32));
#pragma unroll
            for (int j = 0; j < 4; j++) {
                uint32_t b0 = bb[j >> 1][(j & 1) * 2];
                uint32_t b1 = bb[j >> 1][(j & 1) * 2 + 1];
#pragma unroll
                for (int i = 0; i < 4; i++) {
                    asm volatile(
                        "mma.sync.aligned.m16n8k16.row.col.f32.f16.f16.f32 "
                        "{%0,%1,%2,%3}, {%4,%5,%6,%7}, {%8,%9}, {%0,%1,%2,%3};"
                        : "+f"(acc[i][j][0]), "+f"(acc[i][j][1]),
                          "+f"(acc[i][j][2]), "+f"(acc[i][j][3])
                        : "r"(a[i][0]), "r"(a[i][1]), "r"(a[i][2]), "r"(a[i][3]),
                          "r"(b0), "r"(b1));
                }
            }
        }
        __syncthreads();
        if (c + 2 < NCHUNK) {
            stage(c + 2, buf);
            asm volatile("cp.async.commit_group;");
        }
    }

    // ---- epilogue: per-sample dropped bias + float2 stores ----
    const float* ub = u_b + b * COUT;
#pragma unroll
    for (int i = 0; i < 4; i++) {
        const int o0 = m0 + wm + i * 16 + row;
        const float bv0 = (ub[o0]     > PDROP) ? bias[o0]     : 0.0f;
        const float bv1 = (ub[o0 + 8] > PDROP) ? bias[o0 + 8] : 0.0f;
#pragma unroll
        for (int j = 0; j < 4; j++) {
            const int nn = wn + j * 8 + 2 * (lane & 3);
            const int yy = y0 + (nn >> 6);
            const int xx = nn & 63;
            float* p0 = out + ((size_t)(b * COUT + o0)     * HH + yy) * WW + xx;
            float* p1 = out + ((size_t)(b * COUT + o0 + 8) * HH + yy) * WW + xx;
            *(float2*)p0 = make_float2(acc[i][j][0] + bv0, acc[i][j][1] + bv0);
            *(float2*)p1 = make_float2(acc[i][j][2] + bv1, acc[i][j][3] + bv1);
        }
    }
}

// ---------------------------------------------------------------------------
extern "C" void kernel_launch(void* const* d_in, const int* in_sizes, int n_in,
                              void* d_out, int out_size) {
    const float* x    = nullptr;   // 16777216
    const float* w    = nullptr;   // 294912
    const float* bias = nullptr;   // 256
    const float* u_w  = nullptr;   // 9437184
    const float* u_b  = nullptr;   // 8192
    for (int i = 0; i < n_in; i++) {
        switch (in_sizes[i]) {
            case 16777216: x    = (const float*)d_in[i]; break;
            case 294912:   w    = (const float*)d_in[i]; break;
            case 256:      bias = (const float*)d_in[i]; break;
            case 9437184:  u_w  = (const float*)d_in[i]; break;
            case 8192:     u_b  = (const float*)d_in[i]; break;
            default: break;
        }
    }
    float* out = (float*)d_out;

    static bool attr_set = false;
    if (!attr_set) {
        cudaFuncSetAttribute(conv_mma, cudaFuncAttributeMaxDynamicSharedMemorySize,
                             SMEM_BYTES);
        attr_set = true;
    }

    prep_w<<<(B_ * COUT * KTOT) / 256, 256>>>(w, u_w);
    prep_x<<<dim3(8, 64, 32), dim3(32, 8)>>>(x);

    dim3 grid(32, 2, 32);   // (n-tile: 2 rows, m-tile, batch)
    conv_mma<<<grid, 256, SMEM_BYTES>>>(bias, u_b, out);
}

// round 17
// speedup vs baseline: 6.6257x; 1.0283x over previous
#include <cuda_runtime.h>
#include <cuda_fp16.h>
#include <cstdint>

#define B_    32
#define CIN   128
#define COUT  256
#define HH    64
#define WW    64
#define TAPS  9
#define PDROP 0.2f

#define KTOT   (TAPS * CIN)     // 1152
#define NCH2   (KTOT / 64)      // 18 chunks of K=64

// fp16 operands in GEMM-friendly layouts (static scratch; no allocs)
__device__ __half g_wA[B_ * COUT * KTOT];        // [b][o][k], k = tap*128+ci  (18.9 MB)
__device__ __half g_xT[B_ * HH * WW * CIN];      // [b][y][x][ci] channel-last (33.5 MB)

__device__ __forceinline__ uint32_t smem_u32(const void* p) {
    uint32_t a;
    asm("{ .reg .u64 t; cvta.to.shared.u64 t, %1; cvt.u32.u64 %0, t; }" : "=r"(a) : "l"(p));
    return a;
}

#define LDSM4(r0, r1, r2, r3, addr)                                             \
    asm volatile("ldmatrix.sync.aligned.m8n8.x4.shared.b16 {%0,%1,%2,%3}, [%4];" \
                 : "=r"(r0), "=r"(r1), "=r"(r2), "=r"(r3) : "r"(addr))

// ---------------------------------------------------------------------------
// prep_w: dropout-mask weights, reorder to [b][o][k] (k fastest), fp16 round
// ---------------------------------------------------------------------------
__global__ void prep_w(const float* __restrict__ w, const float* __restrict__ u_w) {
    int idx = blockIdx.x * 256 + threadIdx.x;        // [b][o][k]
    int k  = idx % KTOT;
    int bo = idx / KTOT;
    int o  = bo % COUT;
    int b  = bo / COUT;
    int t  = k >> 7;
    int ci = k & 127;
    float u  = u_w[((b * COUT + o) * CIN + ci) * TAPS + t];
    float wv = w[(o * CIN + ci) * TAPS + t];
    g_wA[idx] = __float2half_rn((u > PDROP) ? wv : 0.0f);
}

// ---------------------------------------------------------------------------
// prep_x: NCHW -> channel-last [b][y][x][ci], fp16 round
// ---------------------------------------------------------------------------
__global__ void prep_x(const float* __restrict__ x) {
    __shared__ float tile[32][33];
    const int lane = threadIdx.x;                    // 32
    const int ty   = threadIdx.y;                    // 8
    const int x0   = (blockIdx.x & 1) * 32;
    const int ci0  = (blockIdx.x >> 1) * 32;
    const int y    = blockIdx.y;
    const int b    = blockIdx.z;
    const float* xp = x + (((size_t)b * CIN + ci0) * HH + y) * WW + x0;
#pragma unroll
    for (int ii = 0; ii < 4; ii++) {
        int i = ty * 4 + ii;
        tile[i][lane] = xp[(size_t)i * HH * WW + lane];
    }
    __syncthreads();
    __half* op = g_xT + (((size_t)b * HH + y) * WW + x0) * CIN + ci0;
#pragma unroll
    for (int jj = 0; jj < 4; jj++) {
        int j = ty * 4 + jj;
        op[(size_t)j * CIN + lane] = __float2half_rn(tile[lane][j]);
    }
}

// ---------------------------------------------------------------------------
// conv_mma: per-sample implicit-GEMM conv on mma.sync fp16 (HMMA m16n8k16).
// CTA tile M=128 x N=128 x K=1152 in 18 chunks of K=64.
// 3-stage cp.async pipeline, ONE __syncthreads per iteration (stage target
// (c+2)%3 == (c-1)%3, the buffer everyone finished before this barrier).
// smem tiles [128][72] halves (144B = 9x16B rows -> conflict-free LDSM).
// ---------------------------------------------------------------------------
#define TSTRIDE 72                                   // halves per row (144B)
#define TILE_H  (128 * TSTRIDE)                      // halves per tile
#define NSTAGE  3
#define SMEM_BYTES (NSTAGE * 2 * TILE_H * 2)         // 110592

__global__ __launch_bounds__(256, 2)
void conv_mma(const float* __restrict__ bias,
              const float* __restrict__ u_b,
              float* __restrict__ out) {
    extern __shared__ __half smem[];
    __half* As = smem;                               // [3][128][72]
    __half* Bs = smem + NSTAGE * TILE_H;             // [3][128][72]

    const int tid  = threadIdx.x;
    const int wid  = tid >> 5;
    const int lane = tid & 31;
    const int b    = blockIdx.z;
    const int m0   = blockIdx.y * 128;
    const int y0   = blockIdx.x * 2;

    const int wm  = (wid & 1) * 64;                  // warp M offset
    const int wn  = (wid >> 1) * 32;                 // warp N offset
    const int row = lane >> 2;                       // 0..7

    // Per-lane LDSM base addresses (bytes).
    const uint32_t aAddr0 = smem_u32(As) +
        (uint32_t)(((wm + (lane & 15)) * TSTRIDE + (lane >> 4) * 8) * 2);
    const uint32_t bAddr0 = smem_u32(Bs) +
        (uint32_t)(((wn + (lane >> 4) * 8 + (lane & 7)) * TSTRIDE +
                    ((lane >> 3) & 1) * 8) * 2);

    float acc[4][4][4];
#pragma unroll
    for (int i = 0; i < 4; i++)
#pragma unroll
        for (int j = 0; j < 4; j++)
#pragma unroll
            for (int r = 0; r < 4; r++) acc[i][j][r] = 0.0f;

    const __half* wAb = g_wA + (size_t)(b * COUT + m0) * KTOT;
    const __half* xTb = g_xT + (size_t)b * HH * WW * CIN;

    auto stage = [&](int c, int buf) {               // chunk c: K=64 slice
        const int t   = c >> 1;                      // tap
        const int ci0 = (c & 1) * 64;
        const int dy  = t / 3 - 1;
        const int dx  = t % 3 - 1;
        __half* Ab = As + buf * TILE_H;
        __half* Bb = Bs + buf * TILE_H;
#pragma unroll
        for (int it = 0; it < 4; it++) {             // A: 128 rows x 8 quads(16B)
            int q = tid + 256 * it;
            int m = q >> 3, k8 = (q & 7) * 8;
            const __half* src = wAb + (size_t)m * KTOT + c * 64 + k8;
            uint32_t dst = smem_u32(Ab + m * TSTRIDE + k8);
            asm volatile("cp.async.cg.shared.global [%0], [%1], 16;"
                         :: "r"(dst), "l"(src));
        }
#pragma unroll
        for (int it = 0; it < 4; it++) {             // B: 128 pixels x 8 quads
            int q = tid + 256 * it;
            int n = q >> 3, k8 = (q & 7) * 8;
            int yy = y0 + (n >> 6) + dy;
            int xx = (n & 63) + dx;
            bool inb = (yy >= 0 && yy < HH && xx >= 0 && xx < WW);
            const __half* src = xTb + ((size_t)((inb ? yy : 0) * WW + (inb ? xx : 0))) * CIN
                                + ci0 + k8;
            uint32_t dst = smem_u32(Bb + n * TSTRIDE + k8);
            int sz = inb ? 16 : 0;                   // zero-fill halo
            asm volatile("cp.async.cg.shared.global [%0], [%1], 16, %2;"
                         :: "r"(dst), "l"(src), "r"(sz));
        }
    };

    stage(0, 0);
    asm volatile("cp.async.commit_group;");
    stage(1, 1);
    asm volatile("cp.async.commit_group;");

    int buf = 0;
    for (int c = 0; c < NCH2; c++) {
        if (c + 1 < NCH2) asm volatile("cp.async.wait_group 1;");
        else              asm volatile("cp.async.wait_group 0;");
        __syncthreads();                             // single barrier per iter

        const uint32_t aA = aAddr0 + (uint32_t)(buf * TILE_H * 2);
        const uint32_t bA = bAddr0 + (uint32_t)(buf * TILE_H * 2);
#pragma unroll
        for (int ks = 0; ks < 4; ks++) {             // four k16 steps
            uint32_t a[4][4];
#pragma unroll
            for (int i = 0; i < 4; i++)
                LDSM4(a[i][0], a[i][1], a[i][2], a[i][3],
                      aA + (uint32_t)((i * 16 * TSTRIDE) * 2 + ks * 32));
            uint32_t bb[2][4];
#pragma unroll
            for (int j2 = 0; j2 < 2; j2++)
                LDSM4(bb[j2][0], bb[j2][1], bb[j2][2], bb[j2][3],
                      bA + (uint32_t)((j2 * 16 * TSTRIDE) * 2 + ks * 32));
#pragma unroll
            for (int j = 0; j < 4; j++) {
                uint32_t b0 = bb[j >> 1][(j & 1) * 2];
                uint32_t b1 = bb[j >> 1][(j & 1) * 2 + 1];
#pragma unroll
                for (int i = 0; i < 4; i++) {
                    asm volatile(
                        "mma.sync.aligned.m16n8k16.row.col.f32.f16.f16.f32 "
                        "{%0,%1,%2,%3}, {%4,%5,%6,%7}, {%8,%9}, {%0,%1,%2,%3};"
                        : "+f"(acc[i][j][0]), "+f"(acc[i][j][1]),
                          "+f"(acc[i][j][2]), "+f"(acc[i][j][3])
                        : "r"(a[i][0]), "r"(a[i][1]), "r"(a[i][2]), "r"(a[i][3]),
                          "r"(b0), "r"(b1));
                }
            }
        }
        if (c + 2 < NCH2) {
            int sb = buf + 2; if (sb >= NSTAGE) sb -= NSTAGE;   // == (c-1)%3
            stage(c + 2, sb);
            asm volatile("cp.async.commit_group;");
        }
        if (++buf == NSTAGE) buf = 0;
    }

    // ---- epilogue: per-sample dropped bias + float2 stores ----
    const float* ub = u_b + b * COUT;
#pragma unroll
    for (int i = 0; i < 4; i++) {
        const int o0 = m0 + wm + i * 16 + row;
        const float bv0 = (ub[o0]     > PDROP) ? bias[o0]     : 0.0f;
        const float bv1 = (ub[o0 + 8] > PDROP) ? bias[o0 + 8] : 0.0f;
#pragma unroll
        for (int j = 0; j < 4; j++) {
            const int nn = wn + j * 8 + 2 * (lane & 3);
            const int yy = y0 + (nn >> 6);
            const int xx = nn & 63;
            float* p0 = out + ((size_t)(b * COUT + o0)     * HH + yy) * WW + xx;
            float* p1 = out + ((size_t)(b * COUT + o0 + 8) * HH + yy) * WW + xx;
            *(float2*)p0 = make_float2(acc[i][j][0] + bv0, acc[i][j][1] + bv0);
            *(float2*)p1 = make_float2(acc[i][j][2] + bv1, acc[i][j][3] + bv1);
        }
    }
}

// ---------------------------------------------------------------------------
extern "C" void kernel_launch(void* const* d_in, const int* in_sizes, int n_in,
                              void* d_out, int out_size) {
    const float* x    = nullptr;   // 16777216
    const float* w    = nullptr;   // 294912
    const float* bias = nullptr;   // 256
    const float* u_w  = nullptr;   // 9437184
    const float* u_b  = nullptr;   // 8192
    for (int i = 0; i < n_in; i++) {
        switch (in_sizes[i]) {
            case 16777216: x    = (const float*)d_in[i]; break;
            case 294912:   w    = (const float*)d_in[i]; break;
            case 256:      bias = (const float*)d_in[i]; break;
            case 9437184:  u_w  = (const float*)d_in[i]; break;
            case 8192:     u_b  = (const float*)d_in[i]; break;
            default: break;
        }
    }
    float* out = (float*)d_out;

    static bool attr_set = false;
    if (!attr_set) {
        cudaFuncSetAttribute(conv_mma, cudaFuncAttributeMaxDynamicSharedMemorySize,
                             SMEM_BYTES);
        attr_set = true;
    }

    prep_w<<<(B_ * COUT * KTOT) / 256, 256>>>(w, u_w);
    prep_x<<<dim3(8, 64, 32), dim3(32, 8)>>>(x);

    dim3 grid(32, 2, 32);   // (n-tile: 2 rows, m-tile, batch)
    conv_mma<<<grid, 256, SMEM_BYTES>>>(bias, u_b, out);
}